// round 8
// baseline (speedup 1.0000x reference)
#include <cuda_runtime.h>
#include <cuda_fp16.h>
#include <cstdint>

#define NN   20000
#define EE   320000
#define IND  128
#define HD   64
#define NH   4
#define QKVD 256   // NH * HD
#define NL   3
#define NG   128
#define NB   79    // scan blocks: ceil(NN/256)

// ---------------- scratch (device globals) ----------------------------------
__device__ float  g_h0[NN * HD];
__device__ float  g_h1[NN * HD];
__device__ float  g_q[NN * QKVD];
__device__ __half g_kh[NN * QKVD];
__device__ __half g_vh[NN * QKVD];
__device__ float  g_s[NN * HD];
__device__ int    g_cnt[NN];
__device__ int    g_rowptr[NN + 1];
__device__ int    g_cursor[NN];
__device__ int    g_srcs[EE];
__device__ int    g_bsum[128];
__device__ int    g_boff[128];
__device__ int    g_use32;

__device__ __forceinline__ float* buf_sel(int s) {
    return s == 0 ? g_h0 : g_h1;
}

__device__ __forceinline__ int clampN(int i) {
    return i < 0 ? 0 : (i >= NN ? NN - 1 : i);
}
__device__ __forceinline__ int idx_at(const void* p, int i) {
    if (g_use32) return clampN(((const int*)p)[i]);
    return clampN((int)((const long long*)p)[i]);
}

// ---------------- dtype detection -------------------------------------------
__global__ void k_detect(const void* __restrict__ ei) {
    const long long* p = (const long long*)ei;
    int t = threadIdx.x;
    long long v = p[t];
    unsigned bad = __ballot_sync(0xffffffffu, v < 0 || v >= (long long)NN);
    if (t == 0) g_use32 = (bad != 0u) ? 1 : 0;
}

// ---------------- CSR build -------------------------------------------------
__global__ void k_zero_cnt() {
    int i = blockIdx.x * blockDim.x + threadIdx.x;
    if (i < NN) g_cnt[i] = 0;
}

__global__ void k_count(const void* __restrict__ ei) {
    int e = blockIdx.x * blockDim.x + threadIdx.x;
    if (e < EE) atomicAdd(&g_cnt[idx_at(ei, EE + e)], 1);
}

__global__ void k_scan1() {
    __shared__ int ws[8];
    int t = threadIdx.x, lane = t & 31, wid = t >> 5;
    int i = blockIdx.x * 256 + t;
    int v = (i < NN) ? g_cnt[i] : 0;
    int s = v;
    #pragma unroll
    for (int d = 16; d > 0; d >>= 1) s += __shfl_xor_sync(0xffffffffu, s, d);
    if (lane == 0) ws[wid] = s;
    __syncthreads();
    if (t < 8) {
        int x = ws[t];
        #pragma unroll
        for (int d = 4; d > 0; d >>= 1) x += __shfl_xor_sync(0xffu, x, d);
        if (t == 0) g_bsum[blockIdx.x] = x;
    }
}

__global__ void k_scan2() {
    __shared__ int wsum[4];
    int t = threadIdx.x, lane = t & 31, wid = t >> 5;
    int v = (t < NB) ? g_bsum[t] : 0;
    int incl = v;
    #pragma unroll
    for (int d = 1; d < 32; d <<= 1) {
        int nb = __shfl_up_sync(0xffffffffu, incl, d);
        if (lane >= d) incl += nb;
    }
    if (lane == 31) wsum[wid] = incl;
    __syncthreads();
    int off = 0;
    for (int w = 0; w < wid; w++) off += wsum[w];
    if (t < NB) g_boff[t] = off + incl - v;
}

__global__ void k_scan3() {
    __shared__ int wincl[8];
    int t = threadIdx.x, lane = t & 31, wid = t >> 5;
    int i = blockIdx.x * 256 + t;
    int v = (i < NN) ? g_cnt[i] : 0;
    int incl = v;
    #pragma unroll
    for (int d = 1; d < 32; d <<= 1) {
        int nb = __shfl_up_sync(0xffffffffu, incl, d);
        if (lane >= d) incl += nb;
    }
    if (lane == 31) wincl[wid] = incl;
    __syncthreads();
    int woff = 0;
    for (int w = 0; w < wid; w++) woff += wincl[w];
    int excl = g_boff[blockIdx.x] + woff + incl - v;
    if (i < NN) {
        g_cursor[i] = excl;
        g_rowptr[i + 1] = excl + v;
        if (i == 0) g_rowptr[0] = 0;
    }
}

__global__ void k_scatter(const void* __restrict__ ei) {
    int e = blockIdx.x * blockDim.x + threadIdx.x;
    if (e < EE) {
        int d   = idx_at(ei, EE + e);
        int pos = atomicAdd(&g_cursor[d], 1);
        g_srcs[pos] = idx_at(ei, e);
    }
}

// ---------------- TF32 tensor-core GEMM -------------------------------------
__device__ __forceinline__ uint32_t f2tf32(float f) {
    uint32_t u;
    asm("cvt.rna.tf32.f32 %0, %1;" : "=r"(u) : "f"(f));
    return u;
}

__device__ __forceinline__ void mma_tf32(float& c0, float& c1, float& c2, float& c3,
                                         uint32_t a0, uint32_t a1, uint32_t a2, uint32_t a3,
                                         uint32_t b0, uint32_t b1) {
    asm volatile(
        "mma.sync.aligned.m16n8k8.row.col.f32.tf32.tf32.f32 "
        "{%0,%1,%2,%3},{%4,%5,%6,%7},{%8,%9},{%0,%1,%2,%3};"
        : "+f"(c0), "+f"(c1), "+f"(c2), "+f"(c3)
        : "r"(a0), "r"(a1), "r"(a2), "r"(a3), "r"(b0), "r"(b1));
}

// C[64x64] tile, 4 warps (2m x 2n), warp tile m32n32 (2 m16 sub-frags x 4 n8).
// 128 threads. tf32 conversion at smem store; inner loop pure LDS + HMMA.
__device__ __forceinline__ void gemm_tile_tf32(
    const float* __restrict__ A, const float* __restrict__ W,
    const float* __restrict__ bias, float* __restrict__ C, __half* __restrict__ Ch,
    int n, int K, int Mw, int Mc, int row0, int colW, int colC) {

    __shared__ uint32_t As[64][68];
    __shared__ uint32_t Bs[64][68];

    int tid  = threadIdx.x;
    int lane = tid & 31;
    int wid  = tid >> 5;
    int wm   = wid & 1;          // rows wm*32
    int wn   = wid >> 1;         // cols wn*32
    int g    = lane >> 2;
    int tg   = lane & 3;

    float acc[2][4][4] = {};

    for (int kt = 0; kt < K; kt += 64) {
        #pragma unroll
        for (int i = 0; i < 8; i++) {
            int idx = i * 128 + tid;
            int r = idx >> 4, c4 = idx & 15;
            float4 av = make_float4(0.f, 0.f, 0.f, 0.f);
            int gr = row0 + r;
            if (gr < n) av = *(const float4*)(A + (size_t)gr * K + kt + c4 * 4);
            uint4 at;
            at.x = f2tf32(av.x); at.y = f2tf32(av.y);
            at.z = f2tf32(av.z); at.w = f2tf32(av.w);
            *(uint4*)&As[r][c4 * 4] = at;
        }
        #pragma unroll
        for (int i = 0; i < 8; i++) {
            int idx = i * 128 + tid;
            int r = idx >> 4, c4 = idx & 15;
            float4 bv = *(const float4*)(W + (size_t)(kt + r) * Mw + colW + c4 * 4);
            uint4 bt;
            bt.x = f2tf32(bv.x); bt.y = f2tf32(bv.y);
            bt.z = f2tf32(bv.z); bt.w = f2tf32(bv.w);
            *(uint4*)&Bs[r][c4 * 4] = bt;
        }
        __syncthreads();

        #pragma unroll
        for (int ks = 0; ks < 8; ks++) {
            int k0 = ks * 8;
            uint32_t a[2][4];
            #pragma unroll
            for (int s = 0; s < 2; s++) {
                int rb = wm * 32 + s * 16;
                a[s][0] = As[rb + g][k0 + tg];
                a[s][1] = As[rb + g + 8][k0 + tg];
                a[s][2] = As[rb + g][k0 + tg + 4];
                a[s][3] = As[rb + g + 8][k0 + tg + 4];
            }
            #pragma unroll
            for (int j = 0; j < 4; j++) {
                int n0 = wn * 32 + j * 8;
                uint32_t b0 = Bs[k0 + tg][n0 + g];
                uint32_t b1 = Bs[k0 + tg + 4][n0 + g];
                #pragma unroll
                for (int s = 0; s < 2; s++)
                    mma_tf32(acc[s][j][0], acc[s][j][1], acc[s][j][2], acc[s][j][3],
                             a[s][0], a[s][1], a[s][2], a[s][3], b0, b1);
            }
        }
        __syncthreads();
    }

    #pragma unroll
    for (int s = 0; s < 2; s++) {
        #pragma unroll
        for (int j = 0; j < 4; j++) {
            int n0 = wn * 32 + j * 8;
            int cw = colW + n0 + tg * 2;
            int cc = colC + n0 + tg * 2;
            float b0 = bias[cw], b1 = bias[cw + 1];
            int r0 = row0 + wm * 32 + s * 16 + g;
            int r1 = r0 + 8;
            if (Ch) {
                if (r0 < n)
                    *(__half2*)(Ch + (size_t)r0 * Mc + cc) =
                        __floats2half2_rn(acc[s][j][0] + b0, acc[s][j][1] + b1);
                if (r1 < n)
                    *(__half2*)(Ch + (size_t)r1 * Mc + cc) =
                        __floats2half2_rn(acc[s][j][2] + b0, acc[s][j][3] + b1);
            } else {
                if (r0 < n)
                    *(float2*)(C + (size_t)r0 * Mc + cc) =
                        make_float2(acc[s][j][0] + b0, acc[s][j][1] + b1);
                if (r1 < n)
                    *(float2*)(C + (size_t)r1 * Mc + cc) =
                        make_float2(acc[s][j][2] + b0, acc[s][j][3] + b1);
            }
        }
    }
}

__global__ __launch_bounds__(128) void k_gemm_in(const float* __restrict__ x,
                                                 const float* __restrict__ W,
                                                 const float* __restrict__ bias) {
    gemm_tile_tf32(x, W, bias, g_h0, nullptr, NN, IND, HD, HD, blockIdx.x * 64, 0, 0);
}

__global__ __launch_bounds__(128) void k_gemm_qkvs(int a_sel,
        const float* __restrict__ Wq, const float* __restrict__ bq,
        const float* __restrict__ Wk, const float* __restrict__ bk,
        const float* __restrict__ Wv, const float* __restrict__ bv,
        const float* __restrict__ Ws, const float* __restrict__ bs) {
    const float* A = buf_sel(a_sel);
    int ct = blockIdx.y;
    const float* W; const float* bias; float* C; __half* Ch; int M; int col;
    if (ct < 4)       { W = Wq; bias = bq; C = g_q; Ch = nullptr; M = QKVD; col = ct * 64; }
    else if (ct < 8)  { W = Wk; bias = bk; C = nullptr; Ch = g_kh; M = QKVD; col = (ct - 4) * 64; }
    else if (ct < 12) { W = Wv; bias = bv; C = nullptr; Ch = g_vh; M = QKVD; col = (ct - 8) * 64; }
    else              { W = Ws; bias = bs; C = g_s; Ch = nullptr; M = HD;   col = 0; }
    gemm_tile_tf32(A, W, bias, C, Ch, NN, HD, M, M, blockIdx.x * 64, col, col);
}

// ---------------- per-node attention: online softmax, 2-deep pipeline -------
// one warp per node; lane = head*8 + t; lane owns 8 contiguous fp16 columns.
// do_pool != 0: last layer — fuse ReLU + global_add_pool (atomicAdd into out).
__global__ void k_attn(int out_sel, int do_pool,
                       const void* __restrict__ batch, float* __restrict__ out) {
    int node = (blockIdx.x * blockDim.x + threadIdx.x) >> 5;
    if (node >= NN) return;
    int lane = threadIdx.x & 31;
    int h = lane >> 3, t = lane & 7;
    int col = h * 64 + t * 8;

    const float4* qp = (const float4*)(g_q + (size_t)node * QKVD + col);
    float4 qa = qp[0], qb = qp[1];

    int beg = g_rowptr[node], end = g_rowptr[node + 1];

    float m = -1e30f, denom = 0.f;
    float acc[8] = {0.f, 0.f, 0.f, 0.f, 0.f, 0.f, 0.f, 0.f};

    uint4 k0w, v0w, k1w, v1w;
    if (beg < end) {
        int s = g_srcs[beg];
        k0w = *(const uint4*)(g_kh + (size_t)s * QKVD + col);
        v0w = *(const uint4*)(g_vh + (size_t)s * QKVD + col);
    }
    if (beg + 1 < end) {
        int s = g_srcs[beg + 1];
        k1w = *(const uint4*)(g_kh + (size_t)s * QKVD + col);
        v1w = *(const uint4*)(g_vh + (size_t)s * QKVD + col);
    }

#define ATT_STEP(KC, VC)                                                     \
    {                                                                        \
        const __half2* kh = (const __half2*)&(KC);                           \
        float2 kk0 = __half22float2(kh[0]);                                  \
        float2 kk1 = __half22float2(kh[1]);                                  \
        float2 kk2 = __half22float2(kh[2]);                                  \
        float2 kk3 = __half22float2(kh[3]);                                  \
        float d = qa.x * kk0.x + qa.y * kk0.y + qa.z * kk1.x + qa.w * kk1.y  \
                + qb.x * kk2.x + qb.y * kk2.y + qb.z * kk3.x + qb.w * kk3.y; \
        d += __shfl_xor_sync(0xffffffffu, d, 1);                             \
        d += __shfl_xor_sync(0xffffffffu, d, 2);                             \
        d += __shfl_xor_sync(0xffffffffu, d, 4);                             \
        d *= 0.125f;                                                         \
        float nm   = fmaxf(m, d);                                            \
        float corr = __expf(m - nm);                                         \
        float ex   = __expf(d - nm);                                         \
        m = nm;                                                              \
        denom = denom * corr + ex;                                           \
        const __half2* vh = (const __half2*)&(VC);                           \
        float2 vv0 = __half22float2(vh[0]);                                  \
        float2 vv1 = __half22float2(vh[1]);                                  \
        float2 vv2 = __half22float2(vh[2]);                                  \
        float2 vv3 = __half22float2(vh[3]);                                  \
        acc[0] = acc[0] * corr + ex * vv0.x;                                 \
        acc[1] = acc[1] * corr + ex * vv0.y;                                 \
        acc[2] = acc[2] * corr + ex * vv1.x;                                 \
        acc[3] = acc[3] * corr + ex * vv1.y;                                 \
        acc[4] = acc[4] * corr + ex * vv2.x;                                 \
        acc[5] = acc[5] * corr + ex * vv2.y;                                 \
        acc[6] = acc[6] * corr + ex * vv3.x;                                 \
        acc[7] = acc[7] * corr + ex * vv3.y;                                 \
    }

    int p = beg;
    for (; p + 1 < end; p += 2) {
        uint4 kc0 = k0w, vc0 = v0w;
        if (p + 2 < end) {
            int s = g_srcs[p + 2];
            k0w = *(const uint4*)(g_kh + (size_t)s * QKVD + col);
            v0w = *(const uint4*)(g_vh + (size_t)s * QKVD + col);
        }
        ATT_STEP(kc0, vc0);
        uint4 kc1 = k1w, vc1 = v1w;
        if (p + 3 < end) {
            int s = g_srcs[p + 3];
            k1w = *(const uint4*)(g_kh + (size_t)s * QKVD + col);
            v1w = *(const uint4*)(g_vh + (size_t)s * QKVD + col);
        }
        ATT_STEP(kc1, vc1);
    }
    if (p < end) ATT_STEP(k0w, v0w);
#undef ATT_STEP

    float inv = denom > 0.f ? 1.f / denom : 0.f;

    #pragma unroll
    for (int j = 0; j < 8; j++) {
        float o = acc[j] * inv;
        o += __shfl_xor_sync(0xffffffffu, o, 8);
        o += __shfl_xor_sync(0xffffffffu, o, 16);
        acc[j] = o;
    }

    if (h == 0) {
        const float* sp = g_s + (size_t)node * HD + t * 8;
        if (do_pool) {
            int gidx = g_use32 ? ((const int*)batch)[node]
                               : (int)((const long long*)batch)[node];
            gidx = gidx < 0 ? 0 : (gidx >= NG ? NG - 1 : gidx);
            float* op = out + (size_t)gidx * HD + t * 8;
            #pragma unroll
            for (int j = 0; j < 8; j++) {
                float val = fmaxf(0.25f * acc[j] + sp[j], 0.f);
                atomicAdd(&op[j], val);
            }
        } else {
            float* op = buf_sel(out_sel) + (size_t)node * HD + t * 8;
            #pragma unroll
            for (int j = 0; j < 8; j++) {
                float val = 0.25f * acc[j] + sp[j];
                op[j] = fmaxf(val, 0.f);
            }
        }
    }
}

// ---------------- out zero ---------------------------------------------------
__global__ void k_pool_zero(float* out) {
    int i = blockIdx.x * blockDim.x + threadIdx.x;
    if (i < NG * HD) out[i] = 0.f;
}

// ---------------- host ------------------------------------------------------
extern "C" void kernel_launch(void* const* d_in, const int* in_sizes, int n_in,
                              void* d_out, int out_size) {
    (void)in_sizes; (void)n_in; (void)out_size;
    const float* x     = (const float*)d_in[0];
    const void*  ei    = d_in[1];
    const void*  batch = d_in[2];
    const float* lin_W = (const float*)d_in[3];
    const float* lin_b = (const float*)d_in[4];
    const float* Wq = (const float*)d_in[5];
    const float* bq = (const float*)d_in[6];
    const float* Wk = (const float*)d_in[7];
    const float* bk = (const float*)d_in[8];
    const float* Wv = (const float*)d_in[9];
    const float* bv = (const float*)d_in[10];
    const float* Ws = (const float*)d_in[11];
    const float* bs = (const float*)d_in[12];

    // side stream for CSR build + output zeroing (fork/join, capture-legal)
    cudaStream_t s2;
    cudaStreamCreateWithFlags(&s2, cudaStreamNonBlocking);
    cudaEvent_t eFork, eJoin;
    cudaEventCreateWithFlags(&eFork, cudaEventDisableTiming);
    cudaEventCreateWithFlags(&eJoin, cudaEventDisableTiming);

    cudaEventRecord(eFork, 0);
    cudaStreamWaitEvent(s2, eFork, 0);

    k_pool_zero<<<(NG * HD + 255) / 256, 256, 0, s2>>>((float*)d_out);
    k_detect<<<1, 32, 0, s2>>>(ei);
    k_zero_cnt<<<(NN + 255) / 256, 256, 0, s2>>>();
    k_count<<<(EE + 255) / 256, 256, 0, s2>>>(ei);
    k_scan1<<<NB, 256, 0, s2>>>();
    k_scan2<<<1, 128, 0, s2>>>();
    k_scan3<<<NB, 256, 0, s2>>>();
    k_scatter<<<(EE + 255) / 256, 256, 0, s2>>>(ei);
    cudaEventRecord(eJoin, s2);

    const int RT = (NN + 63) / 64;  // 313 row tiles

    k_gemm_in<<<dim3(RT, 1), 128>>>(x, lin_W, lin_b);

    int hin = 0, hou = 1;
    for (int l = 0; l < NL; l++) {
        k_gemm_qkvs<<<dim3(RT, 13), 128>>>(hin,
            Wq + (size_t)l * HD * QKVD, bq + (size_t)l * QKVD,
            Wk + (size_t)l * HD * QKVD, bk + (size_t)l * QKVD,
            Wv + (size_t)l * HD * QKVD, bv + (size_t)l * QKVD,
            Ws + (size_t)l * HD * HD,   bs + (size_t)l * HD);
        if (l == 0) cudaStreamWaitEvent(0, eJoin, 0);   // CSR + zeroed out ready
        k_attn<<<(NN * 32 + 255) / 256, 256>>>(hou, (l == NL - 1) ? 1 : 0,
                                               batch, (float*)d_out);
        int tmp = hin; hin = hou; hou = tmp;
    }
}